// round 15
// baseline (speedup 1.0000x reference)
#include <cuda_runtime.h>
#include <cuda_bf16.h>
#include <math.h>
#include <stdint.h>

#define NSAMP  131072
#define NDIM   512
#define NCOMP  256
#define NCLASS 8
#define NBIN   100

// ---------------- scratch (__device__ globals; device-code access ONLY) ----
__device__ float         g_data0[(size_t)NSAMP * NCOMP];   // data0 (f32, GEMM1 out)
__device__ __nv_bfloat16 g_A2[(size_t)NSAMP * 2 * NCOMP];  // delta [hi|lo] (spline out)
__device__ __nv_bfloat16 g_B1[(size_t)NCOMP * 2 * NDIM];   // 256 x 1024 [hi|lo] wT^T
__device__ __nv_bfloat16 g_B2[(size_t)NDIM * 2 * NCOMP];   // 512 x 512  [hi|lo] wT
__device__ float g_ktx[NCLASS * NBIN * NCOMP];             // knots [c][t][j]
__device__ float g_kty[NCLASS * NBIN * NCOMP];
__device__ float g_ktd[NCLASS * NBIN * NCOMP];
__device__ int   g_idx[NSAMP];
__device__ int   g_cnt[NCLASS];
__device__ int   g_cur[NCLASS];

// ---------------- helpers ---------------------------------------------------
__device__ __forceinline__ void cp16(void* s, const void* g) {
    uint32_t sa = (uint32_t)__cvta_generic_to_shared(s);
    asm volatile("cp.async.ca.shared.global [%0], [%1], 16;" :: "r"(sa), "l"(g));
}
#define CP_COMMIT() asm volatile("cp.async.commit_group;" ::: "memory")
#define CP_WAIT0()  asm volatile("cp.async.wait_group 0;" ::: "memory")

__device__ __forceinline__ void mma16(float* c, const uint32_t* a, const uint32_t* b) {
    asm volatile(
        "mma.sync.aligned.m16n8k16.row.col.f32.bf16.bf16.f32 "
        "{%0,%1,%2,%3}, {%4,%5,%6,%7}, {%8,%9}, {%0,%1,%2,%3};"
        : "+f"(c[0]), "+f"(c[1]), "+f"(c[2]), "+f"(c[3])
        : "r"(a[0]), "r"(a[1]), "r"(a[2]), "r"(a[3]), "r"(b[0]), "r"(b[1]));
}

// k16 in-segment permutation: fragment pairs (k=2lc,2lc+1,2lc+8,2lc+9) become
// 4 consecutive bf16 -> one LDS.64 per fragment.
__host__ __device__ __forceinline__ int permj(int j) {
    return ((j & 7) >> 1) * 4 + ((j >> 3) << 1) + (j & 1);
}

// ---------------- prep: wT -> [hi|lo] bf16 operand layouts ------------------
__global__ void prep_wt(const float* __restrict__ wT) {
    int e = blockIdx.x * 256 + threadIdx.x;    // over 512*256
    int r = e >> 8, c = e & 255;               // r: dim, c: comp
    float v  = wT[e];
    __nv_bfloat16 hi = __float2bfloat16_rn(v);
    __nv_bfloat16 lo = __float2bfloat16_rn(v - __bfloat162float(hi));
    {   // B1 row n=c (comp), k=r (dim); row stride 1024 bf16
        size_t base = (size_t)c * 1024 + (r >> 4) * 32 + permj(r & 15);
        g_B1[base] = hi; g_B1[base + 16] = lo;
    }
    {   // B2 row n=r (dim), k=c (comp); row stride 512 bf16
        size_t base = (size_t)r * 512 + (c >> 4) * 32 + permj(c & 15);
        g_B2[base] = hi; g_B2[base + 16] = lo;
    }
}

// knots [c][j][t] -> [c][t][j]
__global__ void prep_knots(const float* __restrict__ kx, const float* __restrict__ ky,
                           const float* __restrict__ kd) {
    int e = blockIdx.x * 256 + threadIdx.x;    // 8*100*256
    int c = e / (NBIN * NCOMP);
    int rem = e - c * NBIN * NCOMP;
    int t = rem >> 8, j = rem & 255;
    int src = (c * NCOMP + j) * NBIN + t;
    g_ktx[e] = kx[src]; g_kty[e] = ky[src]; g_ktd[e] = kd[src];
}

// class sort
__global__ void prep_zero() {
    if (threadIdx.x < NCLASS) { g_cnt[threadIdx.x] = 0; g_cur[threadIdx.x] = 0; }
}
__global__ void prep_count(const int* __restrict__ label) {
    __shared__ int h[NCLASS];
    if (threadIdx.x < NCLASS) h[threadIdx.x] = 0;
    __syncthreads();
    atomicAdd(&h[label[blockIdx.x * 256 + threadIdx.x]], 1);
    __syncthreads();
    if (threadIdx.x < NCLASS) atomicAdd(&g_cnt[threadIdx.x], h[threadIdx.x]);
}
__global__ void prep_scatter(const int* __restrict__ label) {
    __shared__ int h[NCLASS], base[NCLASS], off[NCLASS];
    if (threadIdx.x < NCLASS) h[threadIdx.x] = 0;
    __syncthreads();
    int i = blockIdx.x * 256 + threadIdx.x;
    int c = label[i];
    int r = atomicAdd(&h[c], 1);               // intra-block rank
    __syncthreads();
    if (threadIdx.x < NCLASS) {
        base[threadIdx.x] = atomicAdd(&g_cur[threadIdx.x], h[threadIdx.x]);
        int o = 0;
        #pragma unroll
        for (int cc = 0; cc < NCLASS; ++cc) if (cc < threadIdx.x) o += g_cnt[cc];
        off[threadIdx.x] = o;
    }
    __syncthreads();
    g_idx[off[c] + base[c] + r] = i;
}

// ---------------- GEMM (128x128 CTA, k32 chunks = 2 k16 sub-stages) --------
// Sub-stage: A 128x48 bf16 + B 128x48 bf16 = 24 KB.  4 sub-stages = 96 KB.
// Row stride 48 keeps fragment LDS bank-conflict-free; cols 32..47 unused.
#define ASTRIDE 48
#define SUBSZ   (128 * ASTRIDE)                // elems per A or B sub-buffer
#define NTHR    256

// EPI=1: g_data0[M,256] = data @ wT           (A=data f32,  B=g_B1)
// EPI=2: out[M,512]     = data + delta @ wT^T (A=g_A2 bf16, B=g_B2)
template<int NCH, int BSTR, int LDA, int EPI>
__global__ __launch_bounds__(NTHR, 2)
void gemm_k(const float* __restrict__ Adat, const float* __restrict__ Dg,
            float* __restrict__ Cg)
{
    constexpr int NTN = 8;                     // 8 x n8 = 64 cols per warp
    constexpr int MI  = 2;                     // 2 x m16 = 32 rows per warp
    extern __shared__ __nv_bfloat16 smb[];

    const int tid = threadIdx.x, lane = tid & 31, wid = tid >> 5;
    const int lr = lane >> 2, lc = lane & 3;
    const int m0 = blockIdx.x * 128;
    const int n0 = blockIdx.y * 128;
    const int mw = (wid >> 1) * 32;            // 4 warp-rows x 32
    const int nw = (wid & 1) * 64;             // 2 warp-cols x 64

    const __nv_bfloat16* Bg = (EPI == 1) ? g_B1 : g_B2;
    float*               Cp = (EPI == 1) ? (float*)g_data0 : Cg;

    float acc[MI][NTN][4];
    #pragma unroll
    for (int mi = 0; mi < MI; ++mi)
        #pragma unroll
        for (int ni = 0; ni < NTN; ++ni)
            #pragma unroll
            for (int q = 0; q < 4; ++q) acc[mi][ni][q] = 0.f;

    float4 a_src[4];

    // ---- staging helpers (k32 chunk ci -> sub-stages st, st+1) ----
    auto stageB = [&](int ci, int st) {
        #pragma unroll
        for (int i = 0; i < 4; ++i) {          // 1024 x 16B transfers
            int idx = tid + i * 256;
            int sub = idx >> 9, r = (idx >> 2) & 127, f = idx & 3;
            cp16(&smb[(size_t)(st + sub) * 2 * SUBSZ + SUBSZ + r * ASTRIDE + f * 8],
                 &Bg[(size_t)(n0 + r) * BSTR + (ci * 2 + sub) * 32 + f * 8]);
        }
    };
    auto stageA_async = [&](int ci, int st) {  // EPI==2: pre-split A via cp.async
        #pragma unroll
        for (int i = 0; i < 4; ++i) {
            int idx = tid + i * 256;
            int sub = idx >> 9, r = (idx >> 2) & 127, f = idx & 3;
            cp16(&smb[(size_t)(st + sub) * 2 * SUBSZ + r * ASTRIDE + f * 8],
                 &g_A2[(size_t)(m0 + r) * LDA + (ci * 2 + sub) * 32 + f * 8]);
        }
    };
    auto ldgA = [&](int ci) {                  // EPI==1: f32 A, k32 = 8 f4/row
        #pragma unroll
        for (int i = 0; i < 4; ++i) {
            int idx = tid + i * 256;
            int row = idx >> 3, fi = idx & 7;
            a_src[i] = *(const float4*)&Adat[(size_t)(m0 + row) * LDA + ci * 32 + fi * 4];
        }
    };
    auto stsA = [&](int st) {
        #pragma unroll
        for (int i = 0; i < 4; ++i) {
            int idx = tid + i * 256;
            int row = idx >> 3, fi = idx & 7;
            int sub = fi >> 2, fi4 = fi & 3;
            __nv_bfloat16* Ab = smb + (size_t)(st + sub) * 2 * SUBSZ;
            const float* v = (const float*)&a_src[i];
            #pragma unroll
            for (int hpair = 0; hpair < 2; ++hpair) {
                int j0 = fi4 * 4 + hpair * 2;
                float v0 = v[hpair * 2], v1 = v[hpair * 2 + 1];
                __nv_bfloat16 h0 = __float2bfloat16_rn(v0);
                __nv_bfloat16 h1 = __float2bfloat16_rn(v1);
                __nv_bfloat16 l0 = __float2bfloat16_rn(v0 - __bfloat162float(h0));
                __nv_bfloat16 l1 = __float2bfloat16_rn(v1 - __bfloat162float(h1));
                int p = row * ASTRIDE + permj(j0);
                *(__nv_bfloat162*)&Ab[p]      = __nv_bfloat162(h0, h1);
                *(__nv_bfloat162*)&Ab[p + 16] = __nv_bfloat162(l0, l1);
            }
        }
    };
    auto computeSub = [&](int s) {             // one k16 sub-stage
        const __nv_bfloat16* Ab = smb + (size_t)s * 2 * SUBSZ;
        const __nv_bfloat16* Bb = Ab + SUBSZ;
        uint32_t aHf[MI][4], aLf[MI][4];
        #pragma unroll
        for (int mi = 0; mi < MI; ++mi) {
            int ar = mw + mi * 16 + lr;
            uint2 h0 = *(const uint2*)&Ab[ar * ASTRIDE + lc * 4];
            uint2 h1 = *(const uint2*)&Ab[(ar + 8) * ASTRIDE + lc * 4];
            aHf[mi][0] = h0.x; aHf[mi][1] = h1.x; aHf[mi][2] = h0.y; aHf[mi][3] = h1.y;
            uint2 l0 = *(const uint2*)&Ab[ar * ASTRIDE + 16 + lc * 4];
            uint2 l1 = *(const uint2*)&Ab[(ar + 8) * ASTRIDE + 16 + lc * 4];
            aLf[mi][0] = l0.x; aLf[mi][1] = l1.x; aLf[mi][2] = l0.y; aLf[mi][3] = l1.y;
        }
        {   // B hi: aH*bH + aL*bH
            uint2 bf[NTN];
            #pragma unroll
            for (int ni = 0; ni < NTN; ++ni)
                bf[ni] = *(const uint2*)&Bb[(nw + ni * 8 + lr) * ASTRIDE + lc * 4];
            #pragma unroll
            for (int mi = 0; mi < MI; ++mi)
                #pragma unroll
                for (int ni = 0; ni < NTN; ++ni)
                    mma16(acc[mi][ni], aHf[mi], (const uint32_t*)&bf[ni]);
            #pragma unroll
            for (int mi = 0; mi < MI; ++mi)
                #pragma unroll
                for (int ni = 0; ni < NTN; ++ni)
                    mma16(acc[mi][ni], aLf[mi], (const uint32_t*)&bf[ni]);
        }
        {   // B lo: aH*bL
            uint2 bf[NTN];
            #pragma unroll
            for (int ni = 0; ni < NTN; ++ni)
                bf[ni] = *(const uint2*)&Bb[(nw + ni * 8 + lr) * ASTRIDE + 16 + lc * 4];
            #pragma unroll
            for (int mi = 0; mi < MI; ++mi)
                #pragma unroll
                for (int ni = 0; ni < NTN; ++ni)
                    mma16(acc[mi][ni], aHf[mi], (const uint32_t*)&bf[ni]);
        }
    };

    // ---- prologue: stage chunk 0 into sub-stages 0,1 ----
    stageB(0, 0);
    if (EPI == 2) { stageA_async(0, 0); CP_COMMIT(); }
    else          { CP_COMMIT(); ldgA(0); stsA(0); }
    CP_WAIT0();
    __syncthreads();

    for (int ci = 0; ci < NCH; ++ci) {
        const int cur = (ci & 1) * 2, nxt = cur ^ 2;
        if (ci + 1 < NCH) {
            stageB(ci + 1, nxt);
            if (EPI == 2) stageA_async(ci + 1, nxt);
            CP_COMMIT();
            if (EPI == 1) ldgA(ci + 1);
        }
        computeSub(cur);
        computeSub(cur + 1);
        if (ci + 1 < NCH) {
            if (EPI == 1) stsA(nxt);
            CP_WAIT0();
        }
        __syncthreads();
    }

    // ---- epilogue ----
    #pragma unroll
    for (int mi = 0; mi < MI; ++mi) {
        int r0 = m0 + mw + mi * 16 + lr;
        #pragma unroll
        for (int ni = 0; ni < NTN; ++ni) {
            int cc = n0 + nw + ni * 8 + 2 * lc;
            if (EPI == 1) {
                *(float2*)&Cp[(size_t)r0 * NCOMP + cc] =
                    make_float2(acc[mi][ni][0], acc[mi][ni][1]);
                *(float2*)&Cp[(size_t)(r0 + 8) * NCOMP + cc] =
                    make_float2(acc[mi][ni][2], acc[mi][ni][3]);
            } else {
                float2 d0 = *(const float2*)&Dg[(size_t)r0 * NDIM + cc];
                float2 d1 = *(const float2*)&Dg[(size_t)(r0 + 8) * NDIM + cc];
                *(float2*)&Cp[(size_t)r0 * NDIM + cc] =
                    make_float2(acc[mi][ni][0] + d0.x, acc[mi][ni][1] + d0.y);
                *(float2*)&Cp[(size_t)(r0 + 8) * NDIM + cc] =
                    make_float2(acc[mi][ni][2] + d1.x, acc[mi][ni][3] + d1.y);
            }
        }
    }
}

// ---------------- spline: class-sorted, smem tables, lane=comp --------------
// Writes delta directly as [hi|lo] bf16 pairs into GEMM2's operand layout.
#define SPB 128                                // blocks per class
__global__ __launch_bounds__(256) void spline_kernel(float* __restrict__ logj)
{
    __shared__ float xs[NBIN * 32], ys[NBIN * 32], ds[NBIN * 32];
    __shared__ float acc_s[1024];
    const int tid = threadIdx.x, lane = tid & 31, wid = tid >> 5;
    const int c = blockIdx.x / SPB, b = blockIdx.x % SPB;
    const int cnt = g_cnt[c];
    int off = 0;
    #pragma unroll
    for (int cc = 0; cc < NCLASS; ++cc) if (cc < c) off += g_cnt[cc];
    const int chunk = (cnt + SPB - 1) / SPB;
    const int s0 = b * chunk;
    const int s1 = min(s0 + chunk, cnt);
    const int nloc = s1 - s0;
    if (nloc <= 0) return;
    for (int i = tid; i < nloc; i += 256) acc_s[i] = 0.f;

    for (int tile = 0; tile < 8; ++tile) {
        __syncthreads();
        const int j0 = tile * 32;
        for (int e = tid; e < NBIN * 32; e += 256) {
            int t = e >> 5, j = e & 31;
            int gi = (c * NBIN + t) * NCOMP + j0 + j;
            xs[e] = g_ktx[gi]; ys[e] = g_kty[gi]; ds[e] = g_ktd[gi];
        }
        __syncthreads();

        const int comp = j0 + lane;
        const size_t aoff = (comp >> 4) * 32 + permj(comp & 15);

        for (int i = s0 + wid; i < s1; i += 8) {
            const int s = g_idx[off + i];
            const float x = g_data0[(size_t)s * NCOMP + comp];
            int id = 0;
            #pragma unroll
            for (int stp = 64; stp >= 1; stp >>= 1) {
                int t = id + stp;
                int ta = min(t, NBIN);
                float kv = xs[(ta - 1) * 32 + lane];
                if (t <= NBIN && kv < x) id = t;
            }
            int k = min(max(id - 1, 0), NBIN - 2);
            float x0 = xs[k * 32 + lane], x1 = xs[(k + 1) * 32 + lane];
            float y0 = ys[k * 32 + lane], y1 = ys[(k + 1) * 32 + lane];
            float da = ds[k * 32 + lane], db = ds[(k + 1) * 32 + lane];
            float w  = x1 - x0, dy = y1 - y0;
            float iw = __fdividef(1.f, w);
            float sv = dy * iw;
            float xi = fminf(fmaxf((x - x0) * iw, 0.f), 1.f);
            float xi1 = 1.f - xi;
            float denom = sv + (da + db - 2.f * sv) * xi * xi1;
            float idn = __fdividef(1.f, denom);
            float y_in = y0 + dy * (sv * xi * xi + da * xi * xi1) * idn;
            float num  = db * xi * xi + 2.f * sv * xi * xi1 + da * xi1 * xi1;
            bool below = (id == 0), above = (id == NBIN);
            float arg = below ? da : (above ? db : sv * sv * num * idn * idn);
            float y   = below ? (y0 + da * (x - x0))
                              : (above ? (y1 + db * (x - x1)) : y_in);
            float ld  = __logf(arg);
            // delta -> pre-split bf16 [hi|lo] in GEMM2's A layout
            float d = y - x;
            __nv_bfloat16 dh = __float2bfloat16_rn(d);
            __nv_bfloat16 dl = __float2bfloat16_rn(d - __bfloat162float(dh));
            size_t ab = (size_t)s * (2 * NCOMP) + aoff;
            g_A2[ab] = dh; g_A2[ab + 16] = dl;
            #pragma unroll
            for (int o = 16; o; o >>= 1) ld += __shfl_down_sync(0xFFFFFFFFu, ld, o);
            if (lane == 0) acc_s[i - s0] += ld;
        }
    }
    __syncthreads();
    for (int i = tid; i < nloc; i += 256)
        logj[g_idx[off + s0 + i]] = acc_s[i];
}

// ---------------- launch ----------------------------------------------------
// gemm1 stays the 4th launch -> lands on ncu's capture slot.
extern "C" void kernel_launch(void* const* d_in, const int* in_sizes, int n_in,
                              void* d_out, int out_size) {
    const float* data  = (const float*)d_in[0];
    const float* wT    = (const float*)d_in[1];
    const float* kx    = (const float*)d_in[2];
    const float* ky    = (const float*)d_in[3];
    const float* kd    = (const float*)d_in[4];
    const int*   label = (const int*)d_in[5];

    float* out  = (float*)d_out;                    // (N, NDIM)
    float* logj = out + (size_t)NSAMP * NDIM;       // (N,)

    constexpr int SMG = 4 * 2 * SUBSZ * 2;          // 96 KB
    cudaFuncSetAttribute((const void*)gemm_k<16, 1024, 512, 1>,
                         cudaFuncAttributeMaxDynamicSharedMemorySize, SMG);
    cudaFuncSetAttribute((const void*)gemm_k<8, 512, 512, 2>,
                         cudaFuncAttributeMaxDynamicSharedMemorySize, SMG);

    prep_wt<<<NDIM * NCOMP / 256, 256>>>(wT);
    prep_knots<<<NCLASS * NBIN * NCOMP / 256, 256>>>(kx, ky, kd);
    prep_zero<<<1, 32>>>();

    gemm_k<16, 1024, 512, 1><<<dim3(NSAMP / 128, NCOMP / 128), NTHR, SMG>>>(
        data, nullptr, nullptr);

    prep_count<<<NSAMP / 256, 256>>>(label);
    prep_scatter<<<NSAMP / 256, 256>>>(label);

    spline_kernel<<<NCLASS * SPB, 256>>>(logj);

    gemm_k<8, 512, 512, 2><<<dim3(NSAMP / 128, NDIM / 128), NTHR, SMG>>>(
        nullptr, data, out);
}

// round 16
// speedup vs baseline: 1.4053x; 1.4053x over previous
#include <cuda_runtime.h>
#include <cuda_bf16.h>
#include <math.h>
#include <stdint.h>

#define NSAMP  131072
#define NDIM   512
#define NCOMP  256
#define NCLASS 8
#define NBIN   100

// ---------------- scratch (__device__ globals; device-code access ONLY) ----
__device__ float         g_data0[(size_t)NSAMP * NCOMP];   // data0 -> delta
__device__ __nv_bfloat16 g_B1[(size_t)NCOMP * 2 * NDIM];   // 256 x 1024 [hi|lo] wT^T
__device__ __nv_bfloat16 g_B2[(size_t)NDIM * 2 * NCOMP];   // 512 x 512  [hi|lo] wT
__device__ float g_ktx[NCLASS * NBIN * NCOMP];             // knots [c][t][j]
__device__ float g_kty[NCLASS * NBIN * NCOMP];
__device__ float g_ktd[NCLASS * NBIN * NCOMP];
__device__ int   g_idx[(size_t)NCLASS * NSAMP];            // fixed per-class regions
__device__ int   g_cur[NCLASS];

// ---------------- helpers ---------------------------------------------------
__device__ __forceinline__ void cp16(void* s, const void* g) {
    uint32_t sa = (uint32_t)__cvta_generic_to_shared(s);
    asm volatile("cp.async.ca.shared.global [%0], [%1], 16;" :: "r"(sa), "l"(g));
}
#define CP_COMMIT() asm volatile("cp.async.commit_group;" ::: "memory")
#define CP_WAIT0()  asm volatile("cp.async.wait_group 0;" ::: "memory")

__device__ __forceinline__ void mma16(float* c, const uint32_t* a, const uint32_t* b) {
    asm volatile(
        "mma.sync.aligned.m16n8k16.row.col.f32.bf16.bf16.f32 "
        "{%0,%1,%2,%3}, {%4,%5,%6,%7}, {%8,%9}, {%0,%1,%2,%3};"
        : "+f"(c[0]), "+f"(c[1]), "+f"(c[2]), "+f"(c[3])
        : "r"(a[0]), "r"(a[1]), "r"(a[2]), "r"(a[3]), "r"(b[0]), "r"(b[1]));
}

// k16 in-segment permutation: fragment pairs (k=2lc,2lc+1,2lc+8,2lc+9) become
// 4 consecutive bf16 -> one LDS.64 per fragment.
__host__ __device__ __forceinline__ int permj(int j) {
    return ((j & 7) >> 1) * 4 + ((j >> 3) << 1) + (j & 1);
}

// ---------------- prep (merged): wT split + knot transpose + zero ----------
__global__ void prep_all(const float* __restrict__ wT,
                         const float* __restrict__ kx,
                         const float* __restrict__ ky,
                         const float* __restrict__ kd) {
    int e = blockIdx.x * 256 + threadIdx.x;    // grid 800*256 = 204800
    if (blockIdx.x == 0 && threadIdx.x < NCLASS) g_cur[threadIdx.x] = 0;
    {   // knots [c][j][t] -> [c][t][j]
        int c = e / (NBIN * NCOMP);
        int rem = e - c * NBIN * NCOMP;
        int t = rem >> 8, j = rem & 255;
        int src = (c * NCOMP + j) * NBIN + t;
        g_ktx[e] = kx[src]; g_kty[e] = ky[src]; g_ktd[e] = kd[src];
    }
    if (e < NDIM * NCOMP) {                    // wT -> [hi|lo] layouts
        int r = e >> 8, c = e & 255;           // r: dim, c: comp
        float v  = wT[e];
        __nv_bfloat16 hi = __float2bfloat16_rn(v);
        __nv_bfloat16 lo = __float2bfloat16_rn(v - __bfloat162float(hi));
        {   // B1 row n=c (comp), k=r (dim); row stride 1024 bf16
            size_t base = (size_t)c * 1024 + (r >> 4) * 32 + permj(r & 15);
            g_B1[base] = hi; g_B1[base + 16] = lo;
        }
        {   // B2 row n=r (dim), k=c (comp); row stride 512 bf16
            size_t base = (size_t)r * 512 + (c >> 4) * 32 + permj(c & 15);
            g_B2[base] = hi; g_B2[base + 16] = lo;
        }
    }
}

// class scatter into fixed per-class regions (no count/offset pass needed)
__global__ void prep_scatter(const int* __restrict__ label) {
    __shared__ int h[NCLASS], base[NCLASS];
    if (threadIdx.x < NCLASS) h[threadIdx.x] = 0;
    __syncthreads();
    int i = blockIdx.x * 256 + threadIdx.x;
    int c = label[i];
    int r = atomicAdd(&h[c], 1);               // intra-block rank
    __syncthreads();
    if (threadIdx.x < NCLASS)
        base[threadIdx.x] = atomicAdd(&g_cur[threadIdx.x], h[threadIdx.x]);
    __syncthreads();
    g_idx[(size_t)c * NSAMP + base[c] + r] = i;
}

// ---------------- GEMM staging (256 threads, 128x128 CTA tile) --------------
// (exact R14 structure: 2-stage double buffer, k16 chunks, 48 KB smem)
#define ASTRIDE 48
#define BSTRIDE_S 48
#define NTHR 256

template<int LDA>
__device__ __forceinline__ void ldgA(const float* __restrict__ Ag, int m0, int ci,
                                     int tid, float4* a_src) {
    #pragma unroll
    for (int i = 0; i < 2; ++i) {
        int idx = tid + i * 256;
        int row = idx >> 2, fi = idx & 3;
        a_src[i] = *(const float4*)&Ag[(size_t)(m0 + row) * LDA + ci * 16 + fi * 4];
    }
}
// A: write [hi | lo] segments
__device__ __forceinline__ void stsA(__nv_bfloat16* __restrict__ Ab, int tid,
                                     const float4* a_src) {
    #pragma unroll
    for (int i = 0; i < 2; ++i) {
        int idx = tid + i * 256;
        int row = idx >> 2, fi = idx & 3;
        const float* v = (const float*)&a_src[i];
        #pragma unroll
        for (int hpair = 0; hpair < 2; ++hpair) {
            int j0 = fi * 4 + hpair * 2;
            float v0 = v[hpair * 2], v1 = v[hpair * 2 + 1];
            __nv_bfloat16 h0 = __float2bfloat16_rn(v0);
            __nv_bfloat16 h1 = __float2bfloat16_rn(v1);
            __nv_bfloat16 l0 = __float2bfloat16_rn(v0 - __bfloat162float(h0));
            __nv_bfloat16 l1 = __float2bfloat16_rn(v1 - __bfloat162float(h1));
            int p = row * ASTRIDE + permj(j0);
            *(__nv_bfloat162*)&Ab[p]      = __nv_bfloat162(h0, h1);
            *(__nv_bfloat162*)&Ab[p + 16] = __nv_bfloat162(l0, l1);
        }
    }
}
template<int BSTR>
__device__ __forceinline__ void cpB(const __nv_bfloat16* __restrict__ Bg, int n0,
                                    int ci, int tid, __nv_bfloat16* __restrict__ Bb) {
    #pragma unroll
    for (int i = 0; i < 2; ++i) {              // 128 rows * 4 = 512 transfers
        int idx = tid + i * 256;
        int row = idx >> 2, f = idx & 3;
        cp16(&Bb[row * BSTRIDE_S + f * 8],
             &Bg[(size_t)(n0 + row) * BSTR + ci * 32 + f * 8]);
    }
}

// ---------------- main GEMM (128x128 CTA, 8 warps, 32x64 warp tile, 2 CTA/SM)
// EPI=1: g_data0[M,256] = data @ wT           (A=data,    B=g_B1, C=g_data0)
// EPI=2: out[M,512]     = data + delta @ wT^T (A=g_data0, B=g_B2, C=out)
template<int NCH, int BSTR, int LDA, int EPI>
__global__ __launch_bounds__(NTHR, 2)
void gemm_k(const float* __restrict__ Adat, const float* __restrict__ Dg,
            float* __restrict__ Cg)
{
    constexpr int NTN = 8;                     // 8 x n8 = 64 cols per warp
    constexpr int MI  = 2;                     // 2 x m16 = 32 rows per warp
    constexpr int ASZ = 128 * ASTRIDE;
    constexpr int BSZ = 128 * BSTRIDE_S;
    constexpr int SSZ = ASZ + BSZ;
    extern __shared__ __nv_bfloat16 smb[];
    __nv_bfloat16* Abuf[2] = { smb, smb + SSZ };
    __nv_bfloat16* Bbuf[2] = { smb + ASZ, smb + SSZ + ASZ };

    const int tid = threadIdx.x, lane = tid & 31, wid = tid >> 5;
    const int lr = lane >> 2, lc = lane & 3;
    const int m0 = blockIdx.x * 128;
    const int n0 = blockIdx.y * 128;
    const int mw = (wid >> 1) * 32;
    const int nw = (wid & 1) * 64;

    const float*         Ag = (EPI == 1) ? Adat : (const float*)g_data0;
    const __nv_bfloat16* Bg = (EPI == 1) ? g_B1 : g_B2;
    float*               Cp = (EPI == 1) ? (float*)g_data0 : Cg;

    float acc[MI][NTN][4];
    #pragma unroll
    for (int mi = 0; mi < MI; ++mi)
        #pragma unroll
        for (int ni = 0; ni < NTN; ++ni)
            #pragma unroll
            for (int q = 0; q < 4; ++q) acc[mi][ni][q] = 0.f;

    float4 a_src[2];

    cpB<BSTR>(Bg, n0, 0, tid, Bbuf[0]);
    CP_COMMIT();
    ldgA<LDA>(Ag, m0, 0, tid, a_src);
    stsA(Abuf[0], tid, a_src);
    CP_WAIT0();
    __syncthreads();

    for (int ci = 0; ci < NCH; ++ci) {
        const int cur = ci & 1, nxt = cur ^ 1;
        if (ci + 1 < NCH) {
            cpB<BSTR>(Bg, n0, ci + 1, tid, Bbuf[nxt]);
            CP_COMMIT();
            ldgA<LDA>(Ag, m0, ci + 1, tid, a_src);
        }
        const __nv_bfloat16* Ab = Abuf[cur];
        const __nv_bfloat16* Bb = Bbuf[cur];

        uint32_t aHf[MI][4], aLf[MI][4];
        #pragma unroll
        for (int mi = 0; mi < MI; ++mi) {
            int ar = mw + mi * 16 + lr;
            uint2 h0 = *(const uint2*)&Ab[ar * ASTRIDE + lc * 4];
            uint2 h1 = *(const uint2*)&Ab[(ar + 8) * ASTRIDE + lc * 4];
            aHf[mi][0] = h0.x; aHf[mi][1] = h1.x; aHf[mi][2] = h0.y; aHf[mi][3] = h1.y;
            uint2 l0 = *(const uint2*)&Ab[ar * ASTRIDE + 16 + lc * 4];
            uint2 l1 = *(const uint2*)&Ab[(ar + 8) * ASTRIDE + 16 + lc * 4];
            aLf[mi][0] = l0.x; aLf[mi][1] = l1.x; aLf[mi][2] = l0.y; aLf[mi][3] = l1.y;
        }
        {   // B hi: aH*bH + aL*bH
            uint2 bf[NTN];
            #pragma unroll
            for (int ni = 0; ni < NTN; ++ni)
                bf[ni] = *(const uint2*)&Bb[(nw + ni * 8 + lr) * BSTRIDE_S + lc * 4];
            #pragma unroll
            for (int mi = 0; mi < MI; ++mi)
                #pragma unroll
                for (int ni = 0; ni < NTN; ++ni)
                    mma16(acc[mi][ni], aHf[mi], (const uint32_t*)&bf[ni]);
            #pragma unroll
            for (int mi = 0; mi < MI; ++mi)
                #pragma unroll
                for (int ni = 0; ni < NTN; ++ni)
                    mma16(acc[mi][ni], aLf[mi], (const uint32_t*)&bf[ni]);
        }
        {   // B lo: aH*bL
            uint2 bf[NTN];
            #pragma unroll
            for (int ni = 0; ni < NTN; ++ni)
                bf[ni] = *(const uint2*)&Bb[(nw + ni * 8 + lr) * BSTRIDE_S + 16 + lc * 4];
            #pragma unroll
            for (int mi = 0; mi < MI; ++mi)
                #pragma unroll
                for (int ni = 0; ni < NTN; ++ni)
                    mma16(acc[mi][ni], aHf[mi], (const uint32_t*)&bf[ni]);
        }

        if (ci + 1 < NCH) { stsA(Abuf[nxt], tid, a_src); CP_WAIT0(); }
        __syncthreads();
    }

    #pragma unroll
    for (int mi = 0; mi < MI; ++mi) {
        int r0 = m0 + mw + mi * 16 + lr;
        #pragma unroll
        for (int ni = 0; ni < NTN; ++ni) {
            int cc = n0 + nw + ni * 8 + 2 * lc;
            if (EPI == 1) {
                *(float2*)&Cp[(size_t)r0 * NCOMP + cc] =
                    make_float2(acc[mi][ni][0], acc[mi][ni][1]);
                *(float2*)&Cp[(size_t)(r0 + 8) * NCOMP + cc] =
                    make_float2(acc[mi][ni][2], acc[mi][ni][3]);
            } else {
                float2 d0 = *(const float2*)&Dg[(size_t)r0 * NDIM + cc];
                float2 d1 = *(const float2*)&Dg[(size_t)(r0 + 8) * NDIM + cc];
                *(float2*)&Cp[(size_t)r0 * NDIM + cc] =
                    make_float2(acc[mi][ni][0] + d0.x, acc[mi][ni][1] + d0.y);
                *(float2*)&Cp[(size_t)(r0 + 8) * NDIM + cc] =
                    make_float2(acc[mi][ni][2] + d1.x, acc[mi][ni][3] + d1.y);
            }
        }
    }
}

// ---------------- spline: class-sorted, smem tables, 2-way ILP --------------
#define SPB 128                                // blocks per class
__global__ __launch_bounds__(256) void spline_kernel(float* __restrict__ logj)
{
    __shared__ float xs[NBIN * 32], ys[NBIN * 32], ds[NBIN * 32];
    __shared__ float acc_s[1024];
    const int tid = threadIdx.x, lane = tid & 31, wid = tid >> 5;
    const int c = blockIdx.x / SPB, b = blockIdx.x % SPB;
    const int cnt = g_cur[c];
    const size_t off = (size_t)c * NSAMP;
    const int chunk = (cnt + SPB - 1) / SPB;
    const int s0 = b * chunk;
    const int s1 = min(s0 + chunk, cnt);
    const int nloc = s1 - s0;
    if (nloc <= 0) return;
    for (int i = tid; i < nloc; i += 256) acc_s[i] = 0.f;

    for (int tile = 0; tile < 8; ++tile) {
        __syncthreads();
        const int j0 = tile * 32;
        for (int e = tid; e < NBIN * 32; e += 256) {
            int t = e >> 5, j = e & 31;
            int gi = (c * NBIN + t) * NCOMP + j0 + j;
            xs[e] = g_ktx[gi]; ys[e] = g_kty[gi]; ds[e] = g_ktd[gi];
        }
        __syncthreads();

        const int comp = j0 + lane;

        auto evalSpline = [&](float x, int id, float& ld_out, float& d_out) {
            int k = min(max(id - 1, 0), NBIN - 2);
            float x0 = xs[k * 32 + lane], x1 = xs[(k + 1) * 32 + lane];
            float y0 = ys[k * 32 + lane], y1 = ys[(k + 1) * 32 + lane];
            float da = ds[k * 32 + lane], db = ds[(k + 1) * 32 + lane];
            float w  = x1 - x0, dy = y1 - y0;
            float iw = __fdividef(1.f, w);
            float sv = dy * iw;
            float xi = fminf(fmaxf((x - x0) * iw, 0.f), 1.f);
            float xi1 = 1.f - xi;
            float denom = sv + (da + db - 2.f * sv) * xi * xi1;
            float idn = __fdividef(1.f, denom);
            float y_in = y0 + dy * (sv * xi * xi + da * xi * xi1) * idn;
            float num  = db * xi * xi + 2.f * sv * xi * xi1 + da * xi1 * xi1;
            bool below = (id == 0), above = (id == NBIN);
            float arg = below ? da : (above ? db : sv * sv * num * idn * idn);
            float y   = below ? (y0 + da * (x - x0))
                              : (above ? (y1 + db * (x - x1)) : y_in);
            ld_out = __logf(arg);
            d_out  = y - x;
        };

        // 2 samples per warp iteration (i and i+8) for MLP on the LDS chain
        for (int i = s0 + wid; i < s1; i += 16) {
            const int i2 = i + 8;
            const bool v2 = (i2 < s1);
            const int sA = g_idx[off + i];
            const int sB = g_idx[off + (v2 ? i2 : i)];
            const size_t giA = (size_t)sA * NCOMP + comp;
            const size_t giB = (size_t)sB * NCOMP + comp;
            const float xA = g_data0[giA];
            const float xB = g_data0[giB];
            int idA = 0, idB = 0;
            #pragma unroll
            for (int stp = 64; stp >= 1; stp >>= 1) {
                int tA = idA + stp, tB = idB + stp;
                float kvA = xs[(min(tA, NBIN) - 1) * 32 + lane];
                float kvB = xs[(min(tB, NBIN) - 1) * 32 + lane];
                if (tA <= NBIN && kvA < xA) idA = tA;
                if (tB <= NBIN && kvB < xB) idB = tB;
            }
            float ldA, dA, ldB, dB;
            evalSpline(xA, idA, ldA, dA);
            evalSpline(xB, idB, ldB, dB);
            g_data0[giA] = dA;
            if (v2) g_data0[giB] = dB;
            #pragma unroll
            for (int o = 16; o; o >>= 1) {
                ldA += __shfl_down_sync(0xFFFFFFFFu, ldA, o);
                ldB += __shfl_down_sync(0xFFFFFFFFu, ldB, o);
            }
            if (lane == 0) {
                acc_s[i - s0] += ldA;
                if (v2) acc_s[i2 - s0] += ldB;
            }
        }
    }
    __syncthreads();
    for (int i = tid; i < nloc; i += 256)
        logj[g_idx[off + s0 + i]] = acc_s[i];
}

// ---------------- launch ----------------------------------------------------
// Order: prep_all, scatter, gemm1, spline (our 4th -> ncu capture slot), gemm2.
extern "C" void kernel_launch(void* const* d_in, const int* in_sizes, int n_in,
                              void* d_out, int out_size) {
    const float* data  = (const float*)d_in[0];
    const float* wT    = (const float*)d_in[1];
    const float* kx    = (const float*)d_in[2];
    const float* ky    = (const float*)d_in[3];
    const float* kd    = (const float*)d_in[4];
    const int*   label = (const int*)d_in[5];

    float* out  = (float*)d_out;                    // (N, NDIM)
    float* logj = out + (size_t)NSAMP * NDIM;       // (N,)

    constexpr int SMG = 2 * (128 * ASTRIDE + 128 * BSTRIDE_S) * 2;  // 48 KB
    cudaFuncSetAttribute((const void*)gemm_k<32, 1024, 512, 1>,
                         cudaFuncAttributeMaxDynamicSharedMemorySize, SMG);
    cudaFuncSetAttribute((const void*)gemm_k<16, 512, 256, 2>,
                         cudaFuncAttributeMaxDynamicSharedMemorySize, SMG);

    prep_all<<<NCLASS * NBIN * NCOMP / 256, 256>>>(wT, kx, ky, kd);
    prep_scatter<<<NSAMP / 256, 256>>>(label);

    gemm_k<32, 1024, 512, 1><<<dim3(NSAMP / 128, NCOMP / 128), NTHR, SMG>>>(
        data, nullptr, nullptr);

    spline_kernel<<<NCLASS * SPB, 256>>>(logj);

    gemm_k<16, 512, 256, 2><<<dim3(NSAMP / 128, NDIM / 128), NTHR, SMG>>>(
        nullptr, data, out);
}